// round 1
// baseline (speedup 1.0000x reference)
#include <cuda_runtime.h>
#include <cstdint>
#include <math.h>

// Problem-size capacities (from reference: N=50000, E=800000, D=128, H=8)
#define NMAX 50016
#define EMAX 800032
#define D 128

// ---------------- scratch (device globals; no runtime allocation) ------------
__device__ float g_q[NMAX * D];
__device__ float g_k[NMAX * D];
__device__ float g_v[NMAX * D];
__device__ float g_r[NMAX * D];
__device__ float g_o[NMAX * D];
__device__ float g_gate[NMAX * D];
__device__ float g_cat[NMAX * 3 * D];
__device__ float g_e[(size_t)EMAX * D];
__device__ float g_escore[EMAX * 8];
__device__ float g_z[NMAX * 8];
__device__ int   g_counts[NMAX + 8];
__device__ int   g_off[NMAX + 8];
__device__ int   g_cursor[NMAX + 8];
__device__ int   g_elist[EMAX];

// ---------------- generic SGEMM: C[M,128] = A[M,K] @ W[K,128] + bias ---------
// K in {128, 384}. BM=64 rows/block, 256 threads, 8x4 register tile.
__global__ void sgemm_bias(const float* __restrict__ A, const float* __restrict__ W,
                           const float* __restrict__ bias, float* __restrict__ C,
                           int M, int K)
{
    extern __shared__ float sm[];
    float* As = sm;            // [64][128]
    float* Ws = sm + 64 * 128; // [128][128]

    const int tid = threadIdx.x;
    const int tx = tid & 31;     // column group: cols tx*4..tx*4+3
    const int ty = tid >> 5;     // row group: rows ty*8..ty*8+7
    const int m0 = blockIdx.x * 64;

    float acc[8][4];
#pragma unroll
    for (int r = 0; r < 8; ++r)
#pragma unroll
        for (int c = 0; c < 4; ++c) acc[r][c] = 0.f;

    for (int kt = 0; kt < K; kt += 128) {
        // load A tile 64x128 (float4, coalesced)
#pragma unroll
        for (int i = 0; i < 8; ++i) {
            int lin4 = tid + i * 256;       // float4 index within tile
            int m = lin4 >> 5;
            int kk = (lin4 & 31) << 2;
            float4 v4;
            if (m0 + m < M) v4 = *(const float4*)&A[(size_t)(m0 + m) * K + kt + kk];
            else            v4 = make_float4(0.f, 0.f, 0.f, 0.f);
            *(float4*)&As[m * 128 + kk] = v4;
        }
        // load W tile 128x128
#pragma unroll
        for (int i = 0; i < 16; ++i) {
            int lin4 = tid + i * 256;
            int kk = lin4 >> 5;
            int nn = (lin4 & 31) << 2;
            *(float4*)&Ws[kk * 128 + nn] = *(const float4*)&W[(size_t)(kt + kk) * 128 + nn];
        }
        __syncthreads();

#pragma unroll 8
        for (int kk = 0; kk < 128; ++kk) {
            float4 b4 = *(float4*)&Ws[kk * 128 + (tx << 2)];
#pragma unroll
            for (int r = 0; r < 8; ++r) {
                float a = As[(ty * 8 + r) * 128 + kk];   // warp-broadcast
                acc[r][0] += a * b4.x;
                acc[r][1] += a * b4.y;
                acc[r][2] += a * b4.z;
                acc[r][3] += a * b4.w;
            }
        }
        __syncthreads();
    }

    float4 bb = *(const float4*)&bias[tx << 2];
#pragma unroll
    for (int r = 0; r < 8; ++r) {
        int m = m0 + ty * 8 + r;
        if (m < M) {
            float4 ov;
            ov.x = acc[r][0] + bb.x;
            ov.y = acc[r][1] + bb.y;
            ov.z = acc[r][2] + bb.z;
            ov.w = acc[r][3] + bb.w;
            *(float4*)&C[(size_t)m * 128 + (tx << 2)] = ov;
        }
    }
}

// ---------------- CSR build ---------------------------------------------------
__global__ void hist_kernel(const int* __restrict__ dst, int* __restrict__ counts, int E)
{
    int i = blockIdx.x * blockDim.x + threadIdx.x;
    if (i < E) atomicAdd(&counts[dst[i]], 1);
}

__global__ void scan_kernel(const int* __restrict__ counts, int* __restrict__ off,
                            int* __restrict__ cursor, int N)
{
    __shared__ int ssum[1024];
    int t = threadIdx.x;
    int chunk = (N + 1023) >> 10;
    int begin = t * chunk;
    int end = begin + chunk; if (end > N) end = N;
    int s = 0;
    for (int i = begin; i < end; ++i) s += counts[i];
    ssum[t] = s;
    __syncthreads();
    for (int d = 1; d < 1024; d <<= 1) {
        int v = (t >= d) ? ssum[t - d] : 0;
        __syncthreads();
        ssum[t] += v;
        __syncthreads();
    }
    int run = (t == 0) ? 0 : ssum[t - 1];
    for (int i = begin; i < end; ++i) {
        off[i] = run;
        cursor[i] = run;
        run += counts[i];
    }
    if (t == 1023) off[N] = ssum[1023];
}

__global__ void scatter_kernel(const int* __restrict__ dst, int* __restrict__ cursor,
                               int* __restrict__ elist, int E)
{
    int i = blockIdx.x * blockDim.x + threadIdx.x;
    if (i < E) {
        int p = atomicAdd(&cursor[dst[i]], 1);
        elist[p] = i;
    }
}

// ---------------- edge score: escore[e,h] = exp(q[dst].(k[src]+e)) ------------
__global__ void edge_score(const float* __restrict__ e, const float* __restrict__ q,
                           const float* __restrict__ k, const int* __restrict__ src,
                           const int* __restrict__ dst, float* __restrict__ escore, int E)
{
    int w = (blockIdx.x * blockDim.x + threadIdx.x) >> 5;
    int lane = threadIdx.x & 31;
    if (w >= E) return;
    int s = src[w], dn = dst[w];
    float4 ev = *(const float4*)&e[(size_t)w * 128 + (lane << 2)];
    float4 kv = *(const float4*)&k[(size_t)s * 128 + (lane << 2)];
    float4 qv = *(const float4*)&q[(size_t)dn * 128 + (lane << 2)];
    float p = qv.x * (kv.x + ev.x) + qv.y * (kv.y + ev.y)
            + qv.z * (kv.z + ev.z) + qv.w * (kv.w + ev.w);
    p += __shfl_xor_sync(0xFFFFFFFFu, p, 1);
    p += __shfl_xor_sync(0xFFFFFFFFu, p, 2);
    if ((lane & 3) == 0) escore[(size_t)w * 8 + (lane >> 2)] = expf(p);
}

// ---------------- node aggregate: z + o, CSR gather (warp per node) -----------
__global__ void aggregate(const float* __restrict__ e, const float* __restrict__ v,
                          const float* __restrict__ escore, const int* __restrict__ src,
                          const int* __restrict__ off, const int* __restrict__ elist,
                          float* __restrict__ o, float* __restrict__ z, int N)
{
    int w = (blockIdx.x * blockDim.x + threadIdx.x) >> 5;
    int lane = threadIdx.x & 31;
    if (w >= N) return;
    int hl = lane >> 2;
    int beg = off[w], end = off[w + 1];
    float zl = 0.f;
    float ax = 0.f, ay = 0.f, az = 0.f, aw = 0.f;
    for (int idx = beg; idx < end; ++idx) {
        int eid = elist[idx];
        int s = src[eid];
        float esc = escore[(size_t)eid * 8 + hl];
        float4 ev = *(const float4*)&e[(size_t)eid * 128 + (lane << 2)];
        float4 vv = *(const float4*)&v[(size_t)s * 128 + (lane << 2)];
        zl += esc;
        ax += esc * (ev.x + vv.x);
        ay += esc * (ev.y + vv.y);
        az += esc * (ev.z + vv.z);
        aw += esc * (ev.w + vv.w);
    }
    float sc = 0.25f / (1e-8f + zl);
    float4 ov; ov.x = ax * sc; ov.y = ay * sc; ov.z = az * sc; ov.w = aw * sc;
    *(float4*)&o[(size_t)w * 128 + (lane << 2)] = ov;
    if ((lane & 3) == 0) z[(size_t)w * 8 + hl] = zl;
}

// ---------------- norm_escore output ------------------------------------------
__global__ void norm_out(const float* __restrict__ escore, const float* __restrict__ z,
                         const int* __restrict__ dst, float* __restrict__ out2, int E)
{
    int i = blockIdx.x * blockDim.x + threadIdx.x;
    if (i < E * 8) {
        int eidx = i >> 3;
        int h = i & 7;
        out2[i] = 0.25f * escore[i] / (1e-8f + z[(size_t)dst[eidx] * 8 + h]);
    }
}

// ---------------- cat = [o, r, o-r] -------------------------------------------
__global__ void cat_build(const float* __restrict__ o, const float* __restrict__ r,
                          float* __restrict__ cat, int N)
{
    int i = blockIdx.x * blockDim.x + threadIdx.x;
    if (i >= N * 384) return;
    int n = i / 384;
    int c = i - n * 384;
    float val;
    if (c < 128)      val = o[(size_t)n * 128 + c];
    else if (c < 256) val = r[(size_t)n * 128 + c - 128];
    else              val = o[(size_t)n * 128 + c - 256] - r[(size_t)n * 128 + c - 256];
    cat[i] = val;
}

// ---------------- epilogue: gate mix + LayerNorm + leaky_relu -----------------
__global__ void epilogue(const float* __restrict__ gate_lin, const float* __restrict__ o,
                         const float* __restrict__ r, const float* __restrict__ ln_g,
                         const float* __restrict__ ln_b, float* __restrict__ out)
{
    int n = blockIdx.x;
    int j = threadIdx.x;   // 128 threads
    size_t idx = (size_t)n * 128 + j;
    float gl = gate_lin[idx];
    float b = 1.f / (1.f + expf(-gl));
    float ov = o[idx], rv = r[idx];
    float h = ov + b * (rv - ov);

    // block reduce sum & sumsq over 128
    float s1 = h, s2 = h * h;
#pragma unroll
    for (int d = 16; d; d >>= 1) {
        s1 += __shfl_xor_sync(0xFFFFFFFFu, s1, d);
        s2 += __shfl_xor_sync(0xFFFFFFFFu, s2, d);
    }
    __shared__ float red[8];
    int wid = j >> 5;
    if ((j & 31) == 0) { red[wid] = s1; red[4 + wid] = s2; }
    __syncthreads();
    float sum1 = red[0] + red[1] + red[2] + red[3];
    float sum2 = red[4] + red[5] + red[6] + red[7];
    float mu = sum1 * (1.f / 128.f);
    float var = sum2 * (1.f / 128.f) - mu * mu;
    float ln = (h - mu) * rsqrtf(var + 1e-5f) * ln_g[j] + ln_b[j];
    out[idx] = (ln >= 0.f) ? ln : 0.01f * ln;
}

// ---------------- launch -------------------------------------------------------
extern "C" void kernel_launch(void* const* d_in, const int* in_sizes, int n_in,
                              void* d_out, int out_size)
{
    const float* x   = (const float*)d_in[0];
    const float* y   = (const float*)d_in[1];
    const int*   src = (const int*)d_in[2];
    const int*   dst = (const int*)d_in[3];
    const float* Wq  = (const float*)d_in[4];
    const float* bq  = (const float*)d_in[5];
    const float* Wk  = (const float*)d_in[6];
    const float* bk  = (const float*)d_in[7];
    const float* Wv  = (const float*)d_in[8];
    const float* bv  = (const float*)d_in[9];
    const float* We  = (const float*)d_in[10];
    const float* be  = (const float*)d_in[11];
    const float* Wr  = (const float*)d_in[12];
    const float* br  = (const float*)d_in[13];
    const float* Wg  = (const float*)d_in[14];
    const float* bg  = (const float*)d_in[15];
    const float* lng = (const float*)d_in[16];
    const float* lnb = (const float*)d_in[17];

    const int N = in_sizes[0] / 128;
    const int E = in_sizes[2];

    float *q, *k, *v, *r, *o, *gate, *cat, *e, *escore, *z;
    int *counts, *off, *cursor, *elist;
    void* p;
    cudaGetSymbolAddress(&p, g_q);      q = (float*)p;
    cudaGetSymbolAddress(&p, g_k);      k = (float*)p;
    cudaGetSymbolAddress(&p, g_v);      v = (float*)p;
    cudaGetSymbolAddress(&p, g_r);      r = (float*)p;
    cudaGetSymbolAddress(&p, g_o);      o = (float*)p;
    cudaGetSymbolAddress(&p, g_gate);   gate = (float*)p;
    cudaGetSymbolAddress(&p, g_cat);    cat = (float*)p;
    cudaGetSymbolAddress(&p, g_e);      e = (float*)p;
    cudaGetSymbolAddress(&p, g_escore); escore = (float*)p;
    cudaGetSymbolAddress(&p, g_z);      z = (float*)p;
    cudaGetSymbolAddress(&p, g_counts); counts = (int*)p;
    cudaGetSymbolAddress(&p, g_off);    off = (int*)p;
    cudaGetSymbolAddress(&p, g_cursor); cursor = (int*)p;
    cudaGetSymbolAddress(&p, g_elist);  elist = (int*)p;

    const int SMEM = (64 * 128 + 128 * 128) * 4; // 96 KB
    cudaFuncSetAttribute(sgemm_bias, cudaFuncAttributeMaxDynamicSharedMemorySize, SMEM);

    float* out  = (float*)d_out;
    float* out2 = out + (size_t)N * 128;

    cudaMemsetAsync(counts, 0, (size_t)N * sizeof(int));

    // projections
    sgemm_bias<<<(N + 63) / 64, 256, SMEM>>>(x, Wq, bq, q, N, 128);
    sgemm_bias<<<(N + 63) / 64, 256, SMEM>>>(x, Wk, bk, k, N, 128);
    sgemm_bias<<<(N + 63) / 64, 256, SMEM>>>(x, Wv, bv, v, N, 128);
    sgemm_bias<<<(N + 63) / 64, 256, SMEM>>>(x, Wr, br, r, N, 128);
    sgemm_bias<<<(E + 63) / 64, 256, SMEM>>>(y, We, be, e, E, 128);

    // CSR build
    hist_kernel<<<(E + 255) / 256, 256>>>(dst, counts, E);
    scan_kernel<<<1, 1024>>>(counts, off, cursor, N);
    scatter_kernel<<<(E + 255) / 256, 256>>>(dst, cursor, elist, E);

    // attention
    edge_score<<<(E + 7) / 8, 256>>>(e, q, k, src, dst, escore, E);
    aggregate<<<(N + 7) / 8, 256>>>(e, v, escore, src, off, elist, o, z, N);
    norm_out<<<(E * 8 + 255) / 256, 256>>>(escore, z, dst, out2, E);

    // gated residual + LN
    cat_build<<<(N * 384 + 255) / 256, 256>>>(o, r, cat, N);
    sgemm_bias<<<(N + 63) / 64, 256, SMEM>>>(cat, Wg, bg, gate, N, 384);
    epilogue<<<N, 128>>>(gate, o, r, lng, lnb, out);
}

// round 3
// speedup vs baseline: 1.8259x; 1.8259x over previous
#include <cuda_runtime.h>
#include <cuda_bf16.h>
#include <cstdint>
#include <math.h>

#define NMAX 50016
#define EMAX 800032

// ---------------- scratch (device globals; no runtime allocation) ------------
__device__ float g_q[NMAX * 128];
__device__ float g_k[NMAX * 128];
__device__ float g_v[NMAX * 128];
__device__ float g_r[NMAX * 128];
__device__ float g_o[NMAX * 128];
__device__ float g_gate[NMAX * 128];
__device__ float g_e[(size_t)EMAX * 128];
__device__ float g_escore[EMAX * 8];
__device__ float g_z[NMAX * 8];
__device__ __nv_bfloat16 g_wt[7 * 2 * 16384];   // [w][hi/lo][n*128+k] transposed
__device__ int   g_counts[NMAX + 8];
__device__ int   g_off[NMAX + 8];
__device__ int   g_cursor[NMAX + 8];
__device__ int   g_elist[EMAX];

// ---------------- weight prep: transpose [k][n] -> [n][k], split bf16 hi/lo ---
__global__ void prep_w(const float* __restrict__ W, __nv_bfloat16* __restrict__ oh,
                       __nv_bfloat16* __restrict__ ol)
{
    int i = blockIdx.x * 256 + threadIdx.x;
    if (i < 16384) {
        int n = i >> 7, k = i & 127;
        float f = W[k * 128 + n];
        __nv_bfloat16 h = __float2bfloat16(f);
        oh[i] = h;
        ol[i] = __float2bfloat16(f - __bfloat162float(h));
    }
}

// gate weights: W1 = Wg_top + Wg_bot, W2 = Wg_mid - Wg_bot (transposed + split)
__global__ void prep_gate(const float* __restrict__ Wg,
                          __nv_bfloat16* __restrict__ o1h, __nv_bfloat16* __restrict__ o1l,
                          __nv_bfloat16* __restrict__ o2h, __nv_bfloat16* __restrict__ o2l)
{
    int i = blockIdx.x * 256 + threadIdx.x;
    if (i < 16384) {
        int n = i >> 7, k = i & 127;
        float bot = Wg[2 * 16384 + k * 128 + n];
        float f1 = Wg[k * 128 + n] + bot;
        float f2 = Wg[16384 + k * 128 + n] - bot;
        __nv_bfloat16 h1 = __float2bfloat16(f1);
        o1h[i] = h1;
        o1l[i] = __float2bfloat16(f1 - __bfloat162float(h1));
        __nv_bfloat16 h2 = __float2bfloat16(f2);
        o2h[i] = h2;
        o2l[i] = __float2bfloat16(f2 - __bfloat162float(h2));
    }
}

// ---------------- HMMA split-bf16 GEMM: C[M,128] = A[M,128]@W[128,128] --------
// Wt_h/Wt_l: pre-transposed bf16 [n][k]. flags: bit0 = accumulate C, bit1 = +bias
#define APAD 136
#define SMEM_TC (4 * 128 * APAD * 2)

__global__ __launch_bounds__(256, 1)
void tc_gemm(const float* __restrict__ A,
             const __nv_bfloat16* __restrict__ Wt_h, const __nv_bfloat16* __restrict__ Wt_l,
             const float* __restrict__ bias, float* C, int M, int flags)
{
    extern __shared__ __nv_bfloat16 sm[];
    __nv_bfloat16* Ah = sm;                   // [128][APAD]
    __nv_bfloat16* Al = Ah + 128 * APAD;
    __nv_bfloat16* Bh = Al + 128 * APAD;      // [n=128][APAD] (k-major)
    __nv_bfloat16* Bl = Bh + 128 * APAD;

    const int tid = threadIdx.x;
    const int wid = tid >> 5, lane = tid & 31;
    const int m0 = blockIdx.x * 128;

    // ---- load & convert A tile (coalesced float4) ----
#pragma unroll
    for (int i = 0; i < 16; ++i) {
        int t4 = tid + i * 256;          // 4096 float4 = 128 rows x 32
        int m = t4 >> 5, c4 = t4 & 31;
        float4 v = make_float4(0.f, 0.f, 0.f, 0.f);
        if (m0 + m < M) v = *(const float4*)&A[(size_t)(m0 + m) * 128 + (c4 << 2)];
        __nv_bfloat16 h0 = __float2bfloat16(v.x), h1 = __float2bfloat16(v.y);
        __nv_bfloat16 h2 = __float2bfloat16(v.z), h3 = __float2bfloat16(v.w);
        uint32_t hp0 = (uint32_t)__bfloat16_as_ushort(h0) | ((uint32_t)__bfloat16_as_ushort(h1) << 16);
        uint32_t hp1 = (uint32_t)__bfloat16_as_ushort(h2) | ((uint32_t)__bfloat16_as_ushort(h3) << 16);
        __nv_bfloat16 l0 = __float2bfloat16(v.x - __bfloat162float(h0));
        __nv_bfloat16 l1 = __float2bfloat16(v.y - __bfloat162float(h1));
        __nv_bfloat16 l2 = __float2bfloat16(v.z - __bfloat162float(h2));
        __nv_bfloat16 l3 = __float2bfloat16(v.w - __bfloat162float(h3));
        uint32_t lp0 = (uint32_t)__bfloat16_as_ushort(l0) | ((uint32_t)__bfloat16_as_ushort(l1) << 16);
        uint32_t lp1 = (uint32_t)__bfloat16_as_ushort(l2) | ((uint32_t)__bfloat16_as_ushort(l3) << 16);
        *(uint2*)&Ah[m * APAD + (c4 << 2)] = make_uint2(hp0, hp1);
        *(uint2*)&Al[m * APAD + (c4 << 2)] = make_uint2(lp0, lp1);
    }
    // ---- load B tiles (already bf16 [n][k], coalesced uint4 = 8 bf16) ----
#pragma unroll
    for (int i = 0; i < 8; ++i) {
        int t = tid + i * 256;           // 2048 uint4 = 128 n-rows x 16
        int n = t >> 4, k8 = (t & 15) << 3;
        *(uint4*)&Bh[n * APAD + k8] = *(const uint4*)&Wt_h[n * 128 + k8];
        *(uint4*)&Bl[n * APAD + k8] = *(const uint4*)&Wt_l[n * 128 + k8];
    }
    __syncthreads();

    // warp tiling: 2 (m) x 4 (n); warp tile 64x32
    const int wm = (wid >> 2) * 64;
    const int wn = (wid & 3) * 32;
    const int group = lane >> 2, tig = lane & 3;

    float acc[4][4][4];
#pragma unroll
    for (int a = 0; a < 4; ++a)
#pragma unroll
        for (int b = 0; b < 4; ++b)
#pragma unroll
            for (int c = 0; c < 4; ++c) acc[a][b][c] = 0.f;

    const __nv_bfloat16* Asrc[3] = {Ah, Al, Ah};
    const __nv_bfloat16* Bsrc[3] = {Bh, Bh, Bl};

#pragma unroll
    for (int t = 0; t < 3; ++t) {
        const __nv_bfloat16* As = Asrc[t];
        const __nv_bfloat16* Bs = Bsrc[t];
#pragma unroll
        for (int ks = 0; ks < 8; ++ks) {
            const int k0 = ks * 16 + tig * 2;
            uint32_t afr[4][4];
#pragma unroll
            for (int mt = 0; mt < 4; ++mt) {
                int mr = wm + mt * 16 + group;
                afr[mt][0] = *(const uint32_t*)&As[mr * APAD + k0];
                afr[mt][1] = *(const uint32_t*)&As[(mr + 8) * APAD + k0];
                afr[mt][2] = *(const uint32_t*)&As[mr * APAD + k0 + 8];
                afr[mt][3] = *(const uint32_t*)&As[(mr + 8) * APAD + k0 + 8];
            }
            uint32_t bfr[4][2];
#pragma unroll
            for (int nt = 0; nt < 4; ++nt) {
                int nr = wn + nt * 8 + group;
                bfr[nt][0] = *(const uint32_t*)&Bs[nr * APAD + k0];
                bfr[nt][1] = *(const uint32_t*)&Bs[nr * APAD + k0 + 8];
            }
#pragma unroll
            for (int mt = 0; mt < 4; ++mt)
#pragma unroll
                for (int nt = 0; nt < 4; ++nt) {
                    asm volatile(
                        "mma.sync.aligned.m16n8k16.row.col.f32.bf16.bf16.f32 "
                        "{%0,%1,%2,%3}, {%4,%5,%6,%7}, {%8,%9}, {%0,%1,%2,%3};"
                        : "+f"(acc[mt][nt][0]), "+f"(acc[mt][nt][1]),
                          "+f"(acc[mt][nt][2]), "+f"(acc[mt][nt][3])
                        : "r"(afr[mt][0]), "r"(afr[mt][1]), "r"(afr[mt][2]), "r"(afr[mt][3]),
                          "r"(bfr[nt][0]), "r"(bfr[nt][1]));
                }
        }
    }

    // ---- epilogue ----
#pragma unroll
    for (int mt = 0; mt < 4; ++mt) {
        int r0 = m0 + wm + mt * 16 + group;
        int r1 = r0 + 8;
#pragma unroll
        for (int nt = 0; nt < 4; ++nt) {
            int col = wn + nt * 8 + tig * 2;
            float2 p0 = make_float2(acc[mt][nt][0], acc[mt][nt][1]);
            float2 p1 = make_float2(acc[mt][nt][2], acc[mt][nt][3]);
            if (flags & 2) {
                float2 bb = *(const float2*)&bias[col];
                p0.x += bb.x; p0.y += bb.y;
                p1.x += bb.x; p1.y += bb.y;
            }
            if (r0 < M) {
                if (flags & 1) {
                    float2 c0 = *(float2*)&C[(size_t)r0 * 128 + col];
                    p0.x += c0.x; p0.y += c0.y;
                }
                *(float2*)&C[(size_t)r0 * 128 + col] = p0;
            }
            if (r1 < M) {
                if (flags & 1) {
                    float2 c1 = *(float2*)&C[(size_t)r1 * 128 + col];
                    p1.x += c1.x; p1.y += c1.y;
                }
                *(float2*)&C[(size_t)r1 * 128 + col] = p1;
            }
        }
    }
}

// ---------------- CSR build ---------------------------------------------------
__global__ void hist_kernel(const int* __restrict__ dst, int* __restrict__ counts, int E)
{
    int i = blockIdx.x * blockDim.x + threadIdx.x;
    if (i < E) atomicAdd(&counts[dst[i]], 1);
}

__global__ void scan_kernel(const int* __restrict__ counts, int* __restrict__ off,
                            int* __restrict__ cursor, int N)
{
    __shared__ int ssum[1024];
    int t = threadIdx.x;
    int chunk = (N + 1023) >> 10;
    int begin = t * chunk;
    int end = begin + chunk; if (end > N) end = N;
    int s = 0;
    for (int i = begin; i < end; ++i) s += counts[i];
    ssum[t] = s;
    __syncthreads();
    for (int d = 1; d < 1024; d <<= 1) {
        int v = (t >= d) ? ssum[t - d] : 0;
        __syncthreads();
        ssum[t] += v;
        __syncthreads();
    }
    int run = (t == 0) ? 0 : ssum[t - 1];
    for (int i = begin; i < end; ++i) {
        off[i] = run;
        cursor[i] = run;
        run += counts[i];
    }
    if (t == 1023) off[N] = ssum[1023];
}

__global__ void scatter_kernel(const int* __restrict__ dst, int* __restrict__ cursor,
                               int* __restrict__ elist, int E)
{
    int i = blockIdx.x * blockDim.x + threadIdx.x;
    if (i < E) {
        int p = atomicAdd(&cursor[dst[i]], 1);
        elist[p] = i;
    }
}

// ---------------- edge score: escore[e,h] = exp(q[dst].(k[src]+e)) ------------
__global__ void edge_score(const float* __restrict__ e, const float* __restrict__ q,
                           const float* __restrict__ k, const int* __restrict__ src,
                           const int* __restrict__ dst, float* __restrict__ escore, int E)
{
    int w = (blockIdx.x * blockDim.x + threadIdx.x) >> 5;
    int lane = threadIdx.x & 31;
    if (w >= E) return;
    int s = src[w], dn = dst[w];
    float4 ev = *(const float4*)&e[(size_t)w * 128 + (lane << 2)];
    float4 kv = *(const float4*)&k[(size_t)s * 128 + (lane << 2)];
    float4 qv = *(const float4*)&q[(size_t)dn * 128 + (lane << 2)];
    float p = qv.x * (kv.x + ev.x) + qv.y * (kv.y + ev.y)
            + qv.z * (kv.z + ev.z) + qv.w * (kv.w + ev.w);
    p += __shfl_xor_sync(0xFFFFFFFFu, p, 1);
    p += __shfl_xor_sync(0xFFFFFFFFu, p, 2);
    if ((lane & 3) == 0) escore[(size_t)w * 8 + (lane >> 2)] = expf(p);
}

// ---------------- node aggregate: z + o, CSR gather (warp per node) -----------
__global__ void aggregate(const float* __restrict__ e, const float* __restrict__ v,
                          const float* __restrict__ escore, const int* __restrict__ src,
                          const int* __restrict__ off, const int* __restrict__ elist,
                          float* __restrict__ o, float* __restrict__ z, int N)
{
    int w = (blockIdx.x * blockDim.x + threadIdx.x) >> 5;
    int lane = threadIdx.x & 31;
    if (w >= N) return;
    int hl = lane >> 2;
    int beg = off[w], end = off[w + 1];
    float zl = 0.f;
    float ax = 0.f, ay = 0.f, az = 0.f, aw = 0.f;
    for (int idx = beg; idx < end; ++idx) {
        int eid = elist[idx];
        int s = src[eid];
        float esc = escore[(size_t)eid * 8 + hl];
        float4 ev = *(const float4*)&e[(size_t)eid * 128 + (lane << 2)];
        float4 vv = *(const float4*)&v[(size_t)s * 128 + (lane << 2)];
        zl += esc;
        ax += esc * (ev.x + vv.x);
        ay += esc * (ev.y + vv.y);
        az += esc * (ev.z + vv.z);
        aw += esc * (ev.w + vv.w);
    }
    float sc = 0.25f / (1e-8f + zl);
    float4 ov; ov.x = ax * sc; ov.y = ay * sc; ov.z = az * sc; ov.w = aw * sc;
    *(float4*)&o[(size_t)w * 128 + (lane << 2)] = ov;
    if ((lane & 3) == 0) z[(size_t)w * 8 + hl] = zl;
}

// ---------------- norm_escore output ------------------------------------------
__global__ void norm_out(const float* __restrict__ escore, const float* __restrict__ z,
                         const int* __restrict__ dst, float* __restrict__ out2, int E)
{
    int i = blockIdx.x * blockDim.x + threadIdx.x;
    if (i < E * 8) {
        int eidx = i >> 3;
        int h = i & 7;
        out2[i] = 0.25f * escore[i] / (1e-8f + z[(size_t)dst[eidx] * 8 + h]);
    }
}

// ---------------- epilogue: gate mix + LayerNorm + leaky_relu -----------------
__global__ void epilogue(const float* __restrict__ gate_lin, const float* __restrict__ o,
                         const float* __restrict__ r, const float* __restrict__ ln_g,
                         const float* __restrict__ ln_b, float* __restrict__ out)
{
    int n = blockIdx.x;
    int j = threadIdx.x;   // 128 threads
    size_t idx = (size_t)n * 128 + j;
    float gl = gate_lin[idx];
    float b = 1.f / (1.f + expf(-gl));
    float ov = o[idx], rv = r[idx];
    float h = ov + b * (rv - ov);

    float s1 = h, s2 = h * h;
#pragma unroll
    for (int d = 16; d; d >>= 1) {
        s1 += __shfl_xor_sync(0xFFFFFFFFu, s1, d);
        s2 += __shfl_xor_sync(0xFFFFFFFFu, s2, d);
    }
    __shared__ float red[8];
    int wid = j >> 5;
    if ((j & 31) == 0) { red[wid] = s1; red[4 + wid] = s2; }
    __syncthreads();
    float sum1 = red[0] + red[1] + red[2] + red[3];
    float sum2 = red[4] + red[5] + red[6] + red[7];
    float mu = sum1 * (1.f / 128.f);
    float var = sum2 * (1.f / 128.f) - mu * mu;
    float ln = (h - mu) * rsqrtf(var + 1e-5f) * ln_g[j] + ln_b[j];
    out[idx] = (ln >= 0.f) ? ln : 0.01f * ln;
}

// ---------------- launch -------------------------------------------------------
extern "C" void kernel_launch(void* const* d_in, const int* in_sizes, int n_in,
                              void* d_out, int out_size)
{
    const float* x   = (const float*)d_in[0];
    const float* y   = (const float*)d_in[1];
    const int*   src = (const int*)d_in[2];
    const int*   dst = (const int*)d_in[3];
    const float* Wq  = (const float*)d_in[4];
    const float* bq  = (const float*)d_in[5];
    const float* Wk  = (const float*)d_in[6];
    const float* bk  = (const float*)d_in[7];
    const float* Wv  = (const float*)d_in[8];
    const float* bv  = (const float*)d_in[9];
    const float* We  = (const float*)d_in[10];
    const float* be  = (const float*)d_in[11];
    const float* Wr  = (const float*)d_in[12];
    const float* br  = (const float*)d_in[13];
    const float* Wg  = (const float*)d_in[14];
    const float* bg  = (const float*)d_in[15];
    const float* lng = (const float*)d_in[16];
    const float* lnb = (const float*)d_in[17];

    const int N = in_sizes[0] / 128;
    const int E = in_sizes[2];

    float *q, *k, *v, *r, *o, *gate, *e, *escore, *z;
    __nv_bfloat16* wt;
    int *counts, *off, *cursor, *elist;
    void* p;
    cudaGetSymbolAddress(&p, g_q);      q = (float*)p;
    cudaGetSymbolAddress(&p, g_k);      k = (float*)p;
    cudaGetSymbolAddress(&p, g_v);      v = (float*)p;
    cudaGetSymbolAddress(&p, g_r);      r = (float*)p;
    cudaGetSymbolAddress(&p, g_o);      o = (float*)p;
    cudaGetSymbolAddress(&p, g_gate);   gate = (float*)p;
    cudaGetSymbolAddress(&p, g_e);      e = (float*)p;
    cudaGetSymbolAddress(&p, g_escore); escore = (float*)p;
    cudaGetSymbolAddress(&p, g_z);      z = (float*)p;
    cudaGetSymbolAddress(&p, g_wt);     wt = (__nv_bfloat16*)p;
    cudaGetSymbolAddress(&p, g_counts); counts = (int*)p;
    cudaGetSymbolAddress(&p, g_off);    off = (int*)p;
    cudaGetSymbolAddress(&p, g_cursor); cursor = (int*)p;
    cudaGetSymbolAddress(&p, g_elist);  elist = (int*)p;

    cudaFuncSetAttribute(tc_gemm, cudaFuncAttributeMaxDynamicSharedMemorySize, SMEM_TC);

    float* out  = (float*)d_out;
    float* out2 = out + (size_t)N * 128;

    // weight slots: 0=q 1=k 2=v 3=r 4=e 5=W1 6=W2 ; [slot*2*16384 + {0,16384}]
    __nv_bfloat16* wq_h = wt + 0 * 32768; __nv_bfloat16* wq_l = wq_h + 16384;
    __nv_bfloat16* wk_h = wt + 1 * 32768; __nv_bfloat16* wk_l = wk_h + 16384;
    __nv_bfloat16* wv_h = wt + 2 * 32768; __nv_bfloat16* wv_l = wv_h + 16384;
    __nv_bfloat16* wr_h = wt + 3 * 32768; __nv_bfloat16* wr_l = wr_h + 16384;
    __nv_bfloat16* we_h = wt + 4 * 32768; __nv_bfloat16* we_l = we_h + 16384;
    __nv_bfloat16* w1_h = wt + 5 * 32768; __nv_bfloat16* w1_l = w1_h + 16384;
    __nv_bfloat16* w2_h = wt + 6 * 32768; __nv_bfloat16* w2_l = w2_h + 16384;

    cudaMemsetAsync(counts, 0, (size_t)N * sizeof(int));
    prep_w<<<64, 256>>>(Wq, wq_h, wq_l);
    prep_w<<<64, 256>>>(Wk, wk_h, wk_l);
    prep_w<<<64, 256>>>(Wv, wv_h, wv_l);
    prep_w<<<64, 256>>>(Wr, wr_h, wr_l);
    prep_w<<<64, 256>>>(We, we_h, we_l);
    prep_gate<<<64, 256>>>(Wg, w1_h, w1_l, w2_h, w2_l);

    const int gN = (N + 127) / 128;
    const int gE = (E + 127) / 128;

    // projections (HMMA split-bf16)
    tc_gemm<<<gN, 256, SMEM_TC>>>(x, wq_h, wq_l, bq, q, N, 2);
    tc_gemm<<<gN, 256, SMEM_TC>>>(x, wk_h, wk_l, bk, k, N, 2);
    tc_gemm<<<gN, 256, SMEM_TC>>>(x, wv_h, wv_l, bv, v, N, 2);
    tc_gemm<<<gN, 256, SMEM_TC>>>(x, wr_h, wr_l, br, r, N, 2);
    tc_gemm<<<gE, 256, SMEM_TC>>>(y, we_h, we_l, be, e, E, 2);

    // CSR build
    hist_kernel<<<(E + 255) / 256, 256>>>(dst, counts, E);
    scan_kernel<<<1, 1024>>>(counts, off, cursor, N);
    scatter_kernel<<<(E + 255) / 256, 256>>>(dst, cursor, elist, E);

    // attention
    edge_score<<<(E + 7) / 8, 256>>>(e, q, k, src, dst, escore, E);
    aggregate<<<(N + 7) / 8, 256>>>(e, v, escore, src, off, elist, o, z, N);
    norm_out<<<(E * 8 + 255) / 256, 256>>>(escore, z, dst, out2, E);

    // gated residual: gate = o@W1 + r@W2 + bg  (== cat@Wg + bg)
    tc_gemm<<<gN, 256, SMEM_TC>>>(o, w1_h, w1_l, bg, gate, N, 2);
    tc_gemm<<<gN, 256, SMEM_TC>>>(r, w2_h, w2_l, nullptr, gate, N, 1);
    epilogue<<<N, 128>>>(gate, o, r, lng, lnb, out);
}

// round 4
// speedup vs baseline: 1.8725x; 1.0255x over previous
#include <cuda_runtime.h>
#include <cuda_bf16.h>
#include <cstdint>
#include <math.h>

#define NMAX 50016
#define EMAX 800032

// ---------------- scratch (device globals; no runtime allocation) ------------
__device__ float g_q[NMAX * 128];
__device__ float g_k[NMAX * 128];
__device__ float g_v[NMAX * 128];
__device__ float g_r[NMAX * 128];
__device__ float g_o[NMAX * 128];
__device__ float g_gate[NMAX * 128];
__device__ float g_e[(size_t)EMAX * 128];
__device__ float g_escore[EMAX * 8];
__device__ float g_z[NMAX * 8];
__device__ __nv_bfloat16 g_wt[7 * 2 * 16384];   // [w][hi/lo][n*128+k] transposed
__device__ __nv_bfloat16 g_xh[NMAX * 128];
__device__ __nv_bfloat16 g_xl[NMAX * 128];
__device__ int   g_counts[NMAX + 8];
__device__ int   g_off[NMAX + 8];
__device__ int   g_cursor[NMAX + 8];
__device__ int   g_elist[EMAX];

__device__ __forceinline__ uint32_t smem_u32(const void* p) {
    uint32_t a;
    asm("{ .reg .u64 t; cvta.to.shared.u64 t, %1; cvt.u32.u64 %0, t; }" : "=r"(a) : "l"(p));
    return a;
}
__device__ __forceinline__ void ldsm4(uint32_t* r, uint32_t addr) {
    asm volatile("ldmatrix.sync.aligned.m8n8.x4.shared.b16 {%0,%1,%2,%3}, [%4];"
        : "=r"(r[0]), "=r"(r[1]), "=r"(r[2]), "=r"(r[3]) : "r"(addr));
}
// pack 2 floats -> bf16x2 (x -> low, y -> high)
__device__ __forceinline__ uint32_t cvt2(float x, float y) {
    uint32_t d;
    asm("cvt.rn.bf16x2.f32 %0, %1, %2;" : "=r"(d) : "f"(y), "f"(x));
    return d;
}

// ---------------- weight prep: transpose [k][n] -> [n][k], split bf16 hi/lo ---
__global__ void prep_w(const float* __restrict__ W, __nv_bfloat16* __restrict__ oh,
                       __nv_bfloat16* __restrict__ ol)
{
    int i = blockIdx.x * 256 + threadIdx.x;
    if (i < 16384) {
        int n = i >> 7, k = i & 127;
        float f = W[k * 128 + n];
        __nv_bfloat16 h = __float2bfloat16(f);
        oh[i] = h;
        ol[i] = __float2bfloat16(f - __bfloat162float(h));
    }
}

__global__ void prep_gate(const float* __restrict__ Wg,
                          __nv_bfloat16* __restrict__ o1h, __nv_bfloat16* __restrict__ o1l,
                          __nv_bfloat16* __restrict__ o2h, __nv_bfloat16* __restrict__ o2l)
{
    int i = blockIdx.x * 256 + threadIdx.x;
    if (i < 16384) {
        int n = i >> 7, k = i & 127;
        float bot = Wg[2 * 16384 + k * 128 + n];
        float f1 = Wg[k * 128 + n] + bot;
        float f2 = Wg[16384 + k * 128 + n] - bot;
        __nv_bfloat16 h1 = __float2bfloat16(f1);
        o1h[i] = h1;
        o1l[i] = __float2bfloat16(f1 - __bfloat162float(h1));
        __nv_bfloat16 h2 = __float2bfloat16(f2);
        o2h[i] = h2;
        o2l[i] = __float2bfloat16(f2 - __bfloat162float(h2));
    }
}

// ---------------- pre-split activation x -> bf16 hi/lo -----------------------
__global__ void prep_x(const float* __restrict__ X, __nv_bfloat16* __restrict__ xh,
                       __nv_bfloat16* __restrict__ xl, int n4)
{
    int i = blockIdx.x * 256 + threadIdx.x;
    if (i < n4) {
        float4 v = *(const float4*)&X[(size_t)i * 4];
        uint32_t hp0 = cvt2(v.x, v.y);
        uint32_t hp1 = cvt2(v.z, v.w);
        float lx = v.x - __uint_as_float(hp0 << 16);
        float ly = v.y - __uint_as_float(hp0 & 0xFFFF0000u);
        float lz = v.z - __uint_as_float(hp1 << 16);
        float lw = v.w - __uint_as_float(hp1 & 0xFFFF0000u);
        *(uint2*)&xh[(size_t)i * 4] = make_uint2(hp0, hp1);
        *(uint2*)&xl[(size_t)i * 4] = make_uint2(cvt2(lx, ly), cvt2(lz, lw));
    }
}

// ---------------- HMMA split-bf16 GEMM: C[M,128] = A[M,128]@W[128,128] --------
// flags: bit0 = accumulate C, bit1 = +bias, bit2 = A pre-split (A=Ah, A2=Al bf16)
#define APAD 136
#define ABUF (128 * APAD * 2)          // 34816 bytes per buffer
#define SMEM_TC (4 * ABUF)

__global__ __launch_bounds__(256, 1)
void tc_gemm(const void* __restrict__ A, const void* __restrict__ A2,
             const __nv_bfloat16* __restrict__ Wt_h, const __nv_bfloat16* __restrict__ Wt_l,
             const float* __restrict__ bias, float* C, int M, int flags)
{
    extern __shared__ __nv_bfloat16 sm[];
    __nv_bfloat16* Ah = sm;                   // [128][APAD]
    __nv_bfloat16* Al = Ah + 128 * APAD;
    __nv_bfloat16* Bh = Al + 128 * APAD;      // [n=128][APAD]
    __nv_bfloat16* Bl = Bh + 128 * APAD;

    const int tid = threadIdx.x;
    const int wid = tid >> 5, lane = tid & 31;
    const int m0 = blockIdx.x * 128;

    if (flags & 4) {
        const __nv_bfloat16* Agh = (const __nv_bfloat16*)A;
        const __nv_bfloat16* Agl = (const __nv_bfloat16*)A2;
#pragma unroll
        for (int i = 0; i < 8; ++i) {
            int t = tid + i * 256;           // 2048 uint4 = 128 rows x 16
            int m = t >> 4, c8 = (t & 15) << 3;
            uint4 vh = make_uint4(0, 0, 0, 0), vl = make_uint4(0, 0, 0, 0);
            if (m0 + m < M) {
                vh = *(const uint4*)&Agh[(size_t)(m0 + m) * 128 + c8];
                vl = *(const uint4*)&Agl[(size_t)(m0 + m) * 128 + c8];
            }
            *(uint4*)&Ah[m * APAD + c8] = vh;
            *(uint4*)&Al[m * APAD + c8] = vl;
        }
    } else {
        const float* Ag = (const float*)A;
#pragma unroll
        for (int i = 0; i < 16; ++i) {
            int t4 = tid + i * 256;          // 4096 float4
            int m = t4 >> 5, c4 = t4 & 31;
            float4 v = make_float4(0.f, 0.f, 0.f, 0.f);
            if (m0 + m < M) v = *(const float4*)&Ag[(size_t)(m0 + m) * 128 + (c4 << 2)];
            uint32_t hp0 = cvt2(v.x, v.y);
            uint32_t hp1 = cvt2(v.z, v.w);
            float lx = v.x - __uint_as_float(hp0 << 16);
            float ly = v.y - __uint_as_float(hp0 & 0xFFFF0000u);
            float lz = v.z - __uint_as_float(hp1 << 16);
            float lw = v.w - __uint_as_float(hp1 & 0xFFFF0000u);
            *(uint2*)&Ah[m * APAD + (c4 << 2)] = make_uint2(hp0, hp1);
            *(uint2*)&Al[m * APAD + (c4 << 2)] = make_uint2(cvt2(lx, ly), cvt2(lz, lw));
        }
    }
#pragma unroll
    for (int i = 0; i < 8; ++i) {
        int t = tid + i * 256;
        int n = t >> 4, k8 = (t & 15) << 3;
        *(uint4*)&Bh[n * APAD + k8] = *(const uint4*)&Wt_h[n * 128 + k8];
        *(uint4*)&Bl[n * APAD + k8] = *(const uint4*)&Wt_l[n * 128 + k8];
    }
    __syncthreads();

    // warp tiling: 2 (m) x 4 (n); warp tile 64x32
    const int wm = (wid >> 2) * 64;
    const int wn = (wid & 3) * 32;
    const int group = lane >> 2, tig = lane & 3;

    const uint32_t smb = smem_u32(sm);
    const uint32_t AHs = smb, ALs = smb + ABUF, BHs = smb + 2 * ABUF, BLs = smb + 3 * ABUF;
    // ldmatrix addresses
    const uint32_t a_off = ((wm + (lane & 15)) * APAD + ((lane >> 4) << 3)) * 2;
    const uint32_t b_off = ((wn + ((lane >> 4) << 3) + (lane & 7)) * APAD + (((lane >> 3) & 1) << 3)) * 2;
    const uint32_t MT_STRIDE = 16 * APAD * 2;   // 4352

    float acc[4][4][4];
#pragma unroll
    for (int a = 0; a < 4; ++a)
#pragma unroll
        for (int b = 0; b < 4; ++b)
#pragma unroll
            for (int c = 0; c < 4; ++c) acc[a][b][c] = 0.f;

#pragma unroll
    for (int ks = 0; ks < 8; ++ks) {
        const uint32_t kb = ks * 32;
        uint32_t ah[4][4], al[4][4], bh[2][4], bl[2][4];
#pragma unroll
        for (int mt = 0; mt < 4; ++mt) {
            ldsm4(ah[mt], AHs + a_off + mt * MT_STRIDE + kb);
            ldsm4(al[mt], ALs + a_off + mt * MT_STRIDE + kb);
        }
#pragma unroll
        for (int p = 0; p < 2; ++p) {
            ldsm4(bh[p], BHs + b_off + p * MT_STRIDE + kb);
            ldsm4(bl[p], BLs + b_off + p * MT_STRIDE + kb);
        }
#pragma unroll
        for (int mt = 0; mt < 4; ++mt)
#pragma unroll
            for (int nt = 0; nt < 4; ++nt) {
                const uint32_t* bhp = &bh[nt >> 1][(nt & 1) * 2];
                const uint32_t* blp = &bl[nt >> 1][(nt & 1) * 2];
                asm volatile(
                    "mma.sync.aligned.m16n8k16.row.col.f32.bf16.bf16.f32 "
                    "{%0,%1,%2,%3}, {%4,%5,%6,%7}, {%8,%9}, {%0,%1,%2,%3};"
                    : "+f"(acc[mt][nt][0]), "+f"(acc[mt][nt][1]),
                      "+f"(acc[mt][nt][2]), "+f"(acc[mt][nt][3])
                    : "r"(ah[mt][0]), "r"(ah[mt][1]), "r"(ah[mt][2]), "r"(ah[mt][3]),
                      "r"(bhp[0]), "r"(bhp[1]));
                asm volatile(
                    "mma.sync.aligned.m16n8k16.row.col.f32.bf16.bf16.f32 "
                    "{%0,%1,%2,%3}, {%4,%5,%6,%7}, {%8,%9}, {%0,%1,%2,%3};"
                    : "+f"(acc[mt][nt][0]), "+f"(acc[mt][nt][1]),
                      "+f"(acc[mt][nt][2]), "+f"(acc[mt][nt][3])
                    : "r"(al[mt][0]), "r"(al[mt][1]), "r"(al[mt][2]), "r"(al[mt][3]),
                      "r"(bhp[0]), "r"(bhp[1]));
                asm volatile(
                    "mma.sync.aligned.m16n8k16.row.col.f32.bf16.bf16.f32 "
                    "{%0,%1,%2,%3}, {%4,%5,%6,%7}, {%8,%9}, {%0,%1,%2,%3};"
                    : "+f"(acc[mt][nt][0]), "+f"(acc[mt][nt][1]),
                      "+f"(acc[mt][nt][2]), "+f"(acc[mt][nt][3])
                    : "r"(ah[mt][0]), "r"(ah[mt][1]), "r"(ah[mt][2]), "r"(ah[mt][3]),
                      "r"(blp[0]), "r"(blp[1]));
            }
    }

    // ---- epilogue ----
#pragma unroll
    for (int mt = 0; mt < 4; ++mt) {
        int r0 = m0 + wm + mt * 16 + group;
        int r1 = r0 + 8;
#pragma unroll
        for (int nt = 0; nt < 4; ++nt) {
            int col = wn + nt * 8 + tig * 2;
            float2 p0 = make_float2(acc[mt][nt][0], acc[mt][nt][1]);
            float2 p1 = make_float2(acc[mt][nt][2], acc[mt][nt][3]);
            if (flags & 2) {
                float2 bb = *(const float2*)&bias[col];
                p0.x += bb.x; p0.y += bb.y;
                p1.x += bb.x; p1.y += bb.y;
            }
            if (r0 < M) {
                if (flags & 1) {
                    float2 c0 = *(float2*)&C[(size_t)r0 * 128 + col];
                    p0.x += c0.x; p0.y += c0.y;
                }
                *(float2*)&C[(size_t)r0 * 128 + col] = p0;
            }
            if (r1 < M) {
                if (flags & 1) {
                    float2 c1 = *(float2*)&C[(size_t)r1 * 128 + col];
                    p1.x += c1.x; p1.y += c1.y;
                }
                *(float2*)&C[(size_t)r1 * 128 + col] = p1;
            }
        }
    }
}

// ---------------- CSR build ---------------------------------------------------
__global__ void hist_kernel(const int* __restrict__ dst, int* __restrict__ counts, int E)
{
    int i = blockIdx.x * blockDim.x + threadIdx.x;
    if (i < E) atomicAdd(&counts[dst[i]], 1);
}

__global__ void scan_kernel(const int* __restrict__ counts, int* __restrict__ off,
                            int* __restrict__ cursor, int N)
{
    __shared__ int ssum[1024];
    int t = threadIdx.x;
    int chunk = (N + 1023) >> 10;
    int begin = t * chunk;
    int end = begin + chunk; if (end > N) end = N;
    int s = 0;
    for (int i = begin; i < end; ++i) s += counts[i];
    ssum[t] = s;
    __syncthreads();
    for (int d = 1; d < 1024; d <<= 1) {
        int v = (t >= d) ? ssum[t - d] : 0;
        __syncthreads();
        ssum[t] += v;
        __syncthreads();
    }
    int run = (t == 0) ? 0 : ssum[t - 1];
    for (int i = begin; i < end; ++i) {
        off[i] = run;
        cursor[i] = run;
        run += counts[i];
    }
    if (t == 1023) off[N] = ssum[1023];
}

__global__ void scatter_kernel(const int* __restrict__ dst, int* __restrict__ cursor,
                               int* __restrict__ elist, int E)
{
    int i = blockIdx.x * blockDim.x + threadIdx.x;
    if (i < E) {
        int p = atomicAdd(&cursor[dst[i]], 1);
        elist[p] = i;
    }
}

// ---------------- edge score: escore[e,h] = exp(q[dst].(k[src]+e)) ------------
__global__ void edge_score(const float* __restrict__ e, const float* __restrict__ q,
                           const float* __restrict__ k, const int* __restrict__ src,
                           const int* __restrict__ dst, float* __restrict__ escore, int E)
{
    int w = (blockIdx.x * blockDim.x + threadIdx.x) >> 5;
    int lane = threadIdx.x & 31;
    if (w >= E) return;
    int s = src[w], dn = dst[w];
    float4 ev = *(const float4*)&e[(size_t)w * 128 + (lane << 2)];
    float4 kv = *(const float4*)&k[(size_t)s * 128 + (lane << 2)];
    float4 qv = *(const float4*)&q[(size_t)dn * 128 + (lane << 2)];
    float p = qv.x * (kv.x + ev.x) + qv.y * (kv.y + ev.y)
            + qv.z * (kv.z + ev.z) + qv.w * (kv.w + ev.w);
    p += __shfl_xor_sync(0xFFFFFFFFu, p, 1);
    p += __shfl_xor_sync(0xFFFFFFFFu, p, 2);
    if ((lane & 3) == 0) escore[(size_t)w * 8 + (lane >> 2)] = expf(p);
}

// ---------------- node aggregate: z + o, CSR gather (warp per node) -----------
__global__ void aggregate(const float* __restrict__ e, const float* __restrict__ v,
                          const float* __restrict__ escore, const int* __restrict__ src,
                          const int* __restrict__ off, const int* __restrict__ elist,
                          float* __restrict__ o, float* __restrict__ z, int N)
{
    int w = (blockIdx.x * blockDim.x + threadIdx.x) >> 5;
    int lane = threadIdx.x & 31;
    if (w >= N) return;
    int hl = lane >> 2;
    int beg = off[w], end = off[w + 1];
    float zl = 0.f;
    float ax = 0.f, ay = 0.f, az = 0.f, aw = 0.f;
    for (int idx = beg; idx < end; ++idx) {
        int eid = elist[idx];
        int s = src[eid];
        float esc = escore[(size_t)eid * 8 + hl];
        float4 ev = *(const float4*)&e[(size_t)eid * 128 + (lane << 2)];
        float4 vv = *(const float4*)&v[(size_t)s * 128 + (lane << 2)];
        zl += esc;
        ax += esc * (ev.x + vv.x);
        ay += esc * (ev.y + vv.y);
        az += esc * (ev.z + vv.z);
        aw += esc * (ev.w + vv.w);
    }
    float sc = 0.25f / (1e-8f + zl);
    float4 ov; ov.x = ax * sc; ov.y = ay * sc; ov.z = az * sc; ov.w = aw * sc;
    *(float4*)&o[(size_t)w * 128 + (lane << 2)] = ov;
    if ((lane & 3) == 0) z[(size_t)w * 8 + hl] = zl;
}

// ---------------- norm_escore output ------------------------------------------
__global__ void norm_out(const float* __restrict__ escore, const float* __restrict__ z,
                         const int* __restrict__ dst, float* __restrict__ out2, int E)
{
    int i = blockIdx.x * blockDim.x + threadIdx.x;
    if (i < E * 8) {
        int eidx = i >> 3;
        int h = i & 7;
        out2[i] = 0.25f * escore[i] / (1e-8f + z[(size_t)dst[eidx] * 8 + h]);
    }
}

// ---------------- epilogue: gate mix + LayerNorm + leaky_relu -----------------
__global__ void epilogue(const float* __restrict__ gate_lin, const float* __restrict__ o,
                         const float* __restrict__ r, const float* __restrict__ ln_g,
                         const float* __restrict__ ln_b, float* __restrict__ out)
{
    int n = blockIdx.x;
    int j = threadIdx.x;   // 128 threads
    size_t idx = (size_t)n * 128 + j;
    float gl = gate_lin[idx];
    float b = 1.f / (1.f + expf(-gl));
    float ov = o[idx], rv = r[idx];
    float h = ov + b * (rv - ov);

    float s1 = h, s2 = h * h;
#pragma unroll
    for (int d = 16; d; d >>= 1) {
        s1 += __shfl_xor_sync(0xFFFFFFFFu, s1, d);
        s2 += __shfl_xor_sync(0xFFFFFFFFu, s2, d);
    }
    __shared__ float red[8];
    int wid = j >> 5;
    if ((j & 31) == 0) { red[wid] = s1; red[4 + wid] = s2; }
    __syncthreads();
    float sum1 = red[0] + red[1] + red[2] + red[3];
    float sum2 = red[4] + red[5] + red[6] + red[7];
    float mu = sum1 * (1.f / 128.f);
    float var = sum2 * (1.f / 128.f) - mu * mu;
    float ln = (h - mu) * rsqrtf(var + 1e-5f) * ln_g[j] + ln_b[j];
    out[idx] = (ln >= 0.f) ? ln : 0.01f * ln;
}

// ---------------- launch -------------------------------------------------------
extern "C" void kernel_launch(void* const* d_in, const int* in_sizes, int n_in,
                              void* d_out, int out_size)
{
    const float* x   = (const float*)d_in[0];
    const float* y   = (const float*)d_in[1];
    const int*   src = (const int*)d_in[2];
    const int*   dst = (const int*)d_in[3];
    const float* Wq  = (const float*)d_in[4];
    const float* bq  = (const float*)d_in[5];
    const float* Wk  = (const float*)d_in[6];
    const float* bk  = (const float*)d_in[7];
    const float* Wv  = (const float*)d_in[8];
    const float* bv  = (const float*)d_in[9];
    const float* We  = (const float*)d_in[10];
    const float* be  = (const float*)d_in[11];
    const float* Wr  = (const float*)d_in[12];
    const float* br  = (const float*)d_in[13];
    const float* Wg  = (const float*)d_in[14];
    const float* bg  = (const float*)d_in[15];
    const float* lng = (const float*)d_in[16];
    const float* lnb = (const float*)d_in[17];

    const int N = in_sizes[0] / 128;
    const int E = in_sizes[2];

    float *q, *k, *v, *r, *o, *gate, *e, *escore, *z;
    __nv_bfloat16 *wt, *xh, *xl;
    int *counts, *off, *cursor, *elist;
    void* p;
    cudaGetSymbolAddress(&p, g_q);      q = (float*)p;
    cudaGetSymbolAddress(&p, g_k);      k = (float*)p;
    cudaGetSymbolAddress(&p, g_v);      v = (float*)p;
    cudaGetSymbolAddress(&p, g_r);      r = (float*)p;
    cudaGetSymbolAddress(&p, g_o);      o = (float*)p;
    cudaGetSymbolAddress(&p, g_gate);   gate = (float*)p;
    cudaGetSymbolAddress(&p, g_e);      e = (float*)p;
    cudaGetSymbolAddress(&p, g_escore); escore = (float*)p;
    cudaGetSymbolAddress(&p, g_z);      z = (float*)p;
    cudaGetSymbolAddress(&p, g_wt);     wt = (__nv_bfloat16*)p;
    cudaGetSymbolAddress(&p, g_xh);     xh = (__nv_bfloat16*)p;
    cudaGetSymbolAddress(&p, g_xl);     xl = (__nv_bfloat16*)p;
    cudaGetSymbolAddress(&p, g_counts); counts = (int*)p;
    cudaGetSymbolAddress(&p, g_off);    off = (int*)p;
    cudaGetSymbolAddress(&p, g_cursor); cursor = (int*)p;
    cudaGetSymbolAddress(&p, g_elist);  elist = (int*)p;

    cudaFuncSetAttribute(tc_gemm, cudaFuncAttributeMaxDynamicSharedMemorySize, SMEM_TC);

    float* out  = (float*)d_out;
    float* out2 = out + (size_t)N * 128;

    // weight slots: 0=q 1=k 2=v 3=r 4=e 5=W1 6=W2
    __nv_bfloat16* wq_h = wt + 0 * 32768; __nv_bfloat16* wq_l = wq_h + 16384;
    __nv_bfloat16* wk_h = wt + 1 * 32768; __nv_bfloat16* wk_l = wk_h + 16384;
    __nv_bfloat16* wv_h = wt + 2 * 32768; __nv_bfloat16* wv_l = wv_h + 16384;
    __nv_bfloat16* wr_h = wt + 3 * 32768; __nv_bfloat16* wr_l = wr_h + 16384;
    __nv_bfloat16* we_h = wt + 4 * 32768; __nv_bfloat16* we_l = we_h + 16384;
    __nv_bfloat16* w1_h = wt + 5 * 32768; __nv_bfloat16* w1_l = w1_h + 16384;
    __nv_bfloat16* w2_h = wt + 6 * 32768; __nv_bfloat16* w2_l = w2_h + 16384;

    const int gN = (N + 127) / 128;
    const int gE = (E + 127) / 128;

    // launch order puts the big e-GEMM at index 5 for ncu -s 5 -c 1 capture
    cudaMemsetAsync(counts, 0, (size_t)N * sizeof(int));                 // 0
    prep_w<<<64, 256>>>(We, we_h, we_l);                                 // 1
    prep_x<<<(N * 32 + 255) / 256, 256>>>(x, xh, xl, N * 32);            // 2
    prep_w<<<64, 256>>>(Wq, wq_h, wq_l);                                 // 3
    prep_w<<<64, 256>>>(Wk, wk_h, wk_l);                                 // 4
    tc_gemm<<<gE, 256, SMEM_TC>>>(y, nullptr, we_h, we_l, be, e, E, 2);  // 5 <- profiled
    prep_w<<<64, 256>>>(Wv, wv_h, wv_l);
    prep_w<<<64, 256>>>(Wr, wr_h, wr_l);
    prep_gate<<<64, 256>>>(Wg, w1_h, w1_l, w2_h, w2_l);

    // node projections (pre-split x)
    tc_gemm<<<gN, 256, SMEM_TC>>>(xh, xl, wq_h, wq_l, bq, q, N, 6);
    tc_gemm<<<gN, 256, SMEM_TC>>>(xh, xl, wk_h, wk_l, bk, k, N, 6);
    tc_gemm<<<gN, 256, SMEM_TC>>>(xh, xl, wv_h, wv_l, bv, v, N, 6);
    tc_gemm<<<gN, 256, SMEM_TC>>>(xh, xl, wr_h, wr_l, br, r, N, 6);

    // CSR build
    hist_kernel<<<(E + 255) / 256, 256>>>(dst, counts, E);
    scan_kernel<<<1, 1024>>>(counts, off, cursor, N);
    scatter_kernel<<<(E + 255) / 256, 256>>>(dst, cursor, elist, E);

    // attention
    edge_score<<<(E + 7) / 8, 256>>>(e, q, k, src, dst, escore, E);
    aggregate<<<(N + 7) / 8, 256>>>(e, v, escore, src, off, elist, o, z, N);
    norm_out<<<(E * 8 + 255) / 256, 256>>>(escore, z, dst, out2, E);

    // gated residual: gate = o@W1 + r@W2 + bg
    tc_gemm<<<gN, 256, SMEM_TC>>>(o, nullptr, w1_h, w1_l, bg, gate, N, 2);
    tc_gemm<<<gN, 256, SMEM_TC>>>(r, nullptr, w2_h, w2_l, nullptr, gate, N, 1);
    epilogue<<<N, 128>>>(gate, o, r, lng, lnb, out);
}

// round 5
// speedup vs baseline: 1.9687x; 1.0514x over previous
#include <cuda_runtime.h>
#include <cuda_bf16.h>
#include <cstdint>
#include <math.h>

#define NMAX 50016
#define EMAX 800032

// ---------------- scratch (device globals; no runtime allocation) ------------
__device__ float g_q[NMAX * 128];
__device__ float g_k[NMAX * 128];
__device__ float g_v[NMAX * 128];
__device__ float g_r[NMAX * 128];
__device__ float g_o[NMAX * 128];
__device__ float g_e[(size_t)EMAX * 128];
__device__ float g_escore[EMAX * 8];
__device__ float g_z[NMAX * 8];
__device__ __nv_bfloat16 g_wt[7 * 2 * 16384];   // [slot][hi/lo][n*128+k]
__device__ __nv_bfloat16 g_xh[NMAX * 128];
__device__ __nv_bfloat16 g_xl[NMAX * 128];
__device__ int   g_counts[NMAX + 8];
__device__ int   g_off[NMAX + 8];
__device__ int   g_cursor[NMAX + 8];
__device__ int   g_elist[EMAX];

__device__ __forceinline__ uint32_t smem_u32(const void* p) {
    uint32_t a;
    asm("{ .reg .u64 t; cvta.to.shared.u64 t, %1; cvt.u32.u64 %0, t; }" : "=r"(a) : "l"(p));
    return a;
}
__device__ __forceinline__ void ldsm4(uint32_t* r, uint32_t addr) {
    asm volatile("ldmatrix.sync.aligned.m8n8.x4.shared.b16 {%0,%1,%2,%3}, [%4];"
        : "=r"(r[0]), "=r"(r[1]), "=r"(r[2]), "=r"(r[3]) : "r"(addr));
}
__device__ __forceinline__ uint32_t cvt2(float x, float y) {
    uint32_t d;
    asm("cvt.rn.bf16x2.f32 %0, %1, %2;" : "=r"(d) : "f"(y), "f"(x));
    return d;
}
__device__ __forceinline__ void mma16816(float* c, const uint32_t* a, uint32_t b0, uint32_t b1) {
    asm volatile("mma.sync.aligned.m16n8k16.row.col.f32.bf16.bf16.f32 "
        "{%0,%1,%2,%3}, {%4,%5,%6,%7}, {%8,%9}, {%0,%1,%2,%3};"
        : "+f"(c[0]), "+f"(c[1]), "+f"(c[2]), "+f"(c[3])
        : "r"(a[0]), "r"(a[1]), "r"(a[2]), "r"(a[3]), "r"(b0), "r"(b1));
}

// ---------------- GEMM tile framework: BM=64, 256 thr, warp tile 32x32 --------
#define APAD 136
#define A_BYTES (64 * APAD * 2)     // 17408
#define B_BYTES (128 * APAD * 2)    // 34816
#define SMEM_G (2 * A_BYTES + 2 * B_BYTES)  // 104448
#define OFF_AH 0
#define OFF_AL A_BYTES
#define OFF_BH (2 * A_BYTES)
#define OFF_BL (2 * A_BYTES + B_BYTES)
#define MT_STRIDE (16 * APAD * 2)

// fill A (64 rows) from fp32, splitting to bf16 hi/lo
__device__ __forceinline__ void fill_A_f32(char* sm, const float* Ag, int m0, int M, int tid) {
#pragma unroll
    for (int i = 0; i < 8; ++i) {
        int t4 = tid + i * 256;          // 2048 float4
        int m = t4 >> 5, c4 = t4 & 31;
        float4 v = make_float4(0.f, 0.f, 0.f, 0.f);
        if (m0 + m < M) v = *(const float4*)&Ag[(size_t)(m0 + m) * 128 + (c4 << 2)];
        uint32_t hp0 = cvt2(v.x, v.y), hp1 = cvt2(v.z, v.w);
        float lx = v.x - __uint_as_float(hp0 << 16);
        float ly = v.y - __uint_as_float(hp0 & 0xFFFF0000u);
        float lz = v.z - __uint_as_float(hp1 << 16);
        float lw = v.w - __uint_as_float(hp1 & 0xFFFF0000u);
        int boff = (m * APAD + (c4 << 2)) * 2;
        *(uint2*)(sm + OFF_AH + boff) = make_uint2(hp0, hp1);
        *(uint2*)(sm + OFF_AL + boff) = make_uint2(cvt2(lx, ly), cvt2(lz, lw));
    }
}
// fill A (64 rows) from pre-split bf16 hi/lo
__device__ __forceinline__ void fill_A_bf16(char* sm, const __nv_bfloat16* Agh,
                                            const __nv_bfloat16* Agl, int m0, int M, int tid) {
#pragma unroll
    for (int i = 0; i < 4; ++i) {
        int t = tid + i * 256;           // 1024 uint4 = 64 rows x 16
        int m = t >> 4, c8 = (t & 15) << 3;
        uint4 vh = make_uint4(0, 0, 0, 0), vl = make_uint4(0, 0, 0, 0);
        if (m0 + m < M) {
            vh = *(const uint4*)&Agh[(size_t)(m0 + m) * 128 + c8];
            vl = *(const uint4*)&Agl[(size_t)(m0 + m) * 128 + c8];
        }
        int boff = (m * APAD + c8) * 2;
        *(uint4*)(sm + OFF_AH + boff) = vh;
        *(uint4*)(sm + OFF_AL + boff) = vl;
    }
}
// fill B (128 n-rows) from pre-transposed bf16 hi/lo
__device__ __forceinline__ void fill_B(char* sm, const __nv_bfloat16* Wth,
                                       const __nv_bfloat16* Wtl, int tid) {
#pragma unroll
    for (int i = 0; i < 8; ++i) {
        int t = tid + i * 256;           // 2048 uint4 = 128 x 16
        int n = t >> 4, k8 = (t & 15) << 3;
        int boff = (n * APAD + k8) * 2;
        *(uint4*)(sm + OFF_BH + boff) = *(const uint4*)&Wth[n * 128 + k8];
        *(uint4*)(sm + OFF_BL + boff) = *(const uint4*)&Wtl[n * 128 + k8];
    }
}
// mainloop: 3-term split accumulation, acc[2][4][4]
__device__ __forceinline__ void mma_tile(uint32_t smb, uint32_t a_off, uint32_t b_off,
                                         float acc[2][4][4]) {
    const uint32_t AHs = smb + OFF_AH, ALs = smb + OFF_AL;
    const uint32_t BHs = smb + OFF_BH, BLs = smb + OFF_BL;
#pragma unroll
    for (int ks = 0; ks < 8; ++ks) {
        const uint32_t kb = ks * 32;
        uint32_t ah[2][4], al[2][4], bh[2][4], bl[2][4];
#pragma unroll
        for (int mt = 0; mt < 2; ++mt) {
            ldsm4(ah[mt], AHs + a_off + mt * MT_STRIDE + kb);
            ldsm4(al[mt], ALs + a_off + mt * MT_STRIDE + kb);
        }
#pragma unroll
        for (int p = 0; p < 2; ++p) {
            ldsm4(bh[p], BHs + b_off + p * MT_STRIDE + kb);
            ldsm4(bl[p], BLs + b_off + p * MT_STRIDE + kb);
        }
#pragma unroll
        for (int mt = 0; mt < 2; ++mt)
#pragma unroll
            for (int nt = 0; nt < 4; ++nt) {
                uint32_t b0h = bh[nt >> 1][(nt & 1) * 2], b1h = bh[nt >> 1][(nt & 1) * 2 + 1];
                uint32_t b0l = bl[nt >> 1][(nt & 1) * 2], b1l = bl[nt >> 1][(nt & 1) * 2 + 1];
                mma16816(acc[mt][nt], ah[mt], b0h, b1h);
                mma16816(acc[mt][nt], al[mt], b0h, b1h);
                mma16816(acc[mt][nt], ah[mt], b0l, b1l);
            }
    }
}
#define CLEAR_ACC(acc) \
    _Pragma("unroll") for (int _a = 0; _a < 2; ++_a) \
    _Pragma("unroll") for (int _b = 0; _b < 4; ++_b) \
    _Pragma("unroll") for (int _c = 0; _c < 4; ++_c) acc[_a][_b][_c] = 0.f;

// ---------------- e-GEMM: C = A@W + bias (fp32 A) -----------------------------
__global__ __launch_bounds__(256, 2)
void tc_gemm(const float* __restrict__ A,
             const __nv_bfloat16* __restrict__ Wt_h, const __nv_bfloat16* __restrict__ Wt_l,
             const float* __restrict__ bias, float* __restrict__ C, int M)
{
    extern __shared__ char sm[];
    const int tid = threadIdx.x, wid = tid >> 5, lane = tid & 31;
    const int m0 = blockIdx.x * 64;
    const int wm = (wid >> 2) * 32, wn = (wid & 3) * 32;
    const int group = lane >> 2, tig = lane & 3;

    fill_A_f32(sm, A, m0, M, tid);
    fill_B(sm, Wt_h, Wt_l, tid);
    __syncthreads();

    const uint32_t smb = smem_u32(sm);
    const uint32_t a_off = ((wm + (lane & 15)) * APAD + ((lane >> 4) << 3)) * 2;
    const uint32_t b_off = ((wn + ((lane >> 4) << 3) + (lane & 7)) * APAD + (((lane >> 3) & 1) << 3)) * 2;

    float acc[2][4][4];
    CLEAR_ACC(acc);
    mma_tile(smb, a_off, b_off, acc);

#pragma unroll
    for (int mt = 0; mt < 2; ++mt) {
        int r0 = m0 + wm + mt * 16 + group, r1 = r0 + 8;
#pragma unroll
        for (int nt = 0; nt < 4; ++nt) {
            int col = wn + nt * 8 + tig * 2;
            float2 bb = *(const float2*)&bias[col];
            if (r0 < M) *(float2*)&C[(size_t)r0 * 128 + col] =
                make_float2(acc[mt][nt][0] + bb.x, acc[mt][nt][1] + bb.y);
            if (r1 < M) *(float2*)&C[(size_t)r1 * 128 + col] =
                make_float2(acc[mt][nt][2] + bb.x, acc[mt][nt][3] + bb.y);
        }
    }
}

// ---------------- fused QKVR: 4 GEMMs sharing one A tile ----------------------
__global__ __launch_bounds__(256, 2)
void qkvr_gemm(const __nv_bfloat16* __restrict__ xh, const __nv_bfloat16* __restrict__ xl,
               const __nv_bfloat16* __restrict__ wt,
               const float* __restrict__ bq, const float* __restrict__ bk,
               const float* __restrict__ bv, const float* __restrict__ br,
               float* __restrict__ q, float* __restrict__ k,
               float* __restrict__ v, float* __restrict__ r, int M)
{
    extern __shared__ char sm[];
    const int tid = threadIdx.x, wid = tid >> 5, lane = tid & 31;
    const int m0 = blockIdx.x * 64;
    const int wm = (wid >> 2) * 32, wn = (wid & 3) * 32;
    const int group = lane >> 2, tig = lane & 3;

    fill_A_bf16(sm, xh, xl, m0, M, tid);

    const uint32_t smb = smem_u32(sm);
    const uint32_t a_off = ((wm + (lane & 15)) * APAD + ((lane >> 4) << 3)) * 2;
    const uint32_t b_off = ((wn + ((lane >> 4) << 3) + (lane & 7)) * APAD + (((lane >> 3) & 1) << 3)) * 2;

    const float* bs[4] = {bq, bk, bv, br};
    float* outs[4] = {q, k, v, r};

#pragma unroll
    for (int w = 0; w < 4; ++w) {
        fill_B(sm, wt + w * 32768, wt + w * 32768 + 16384, tid);
        __syncthreads();

        float acc[2][4][4];
        CLEAR_ACC(acc);
        mma_tile(smb, a_off, b_off, acc);

        const float* bias = bs[w];
        float* C = outs[w];
#pragma unroll
        for (int mt = 0; mt < 2; ++mt) {
            int r0 = m0 + wm + mt * 16 + group, r1 = r0 + 8;
#pragma unroll
            for (int nt = 0; nt < 4; ++nt) {
                int col = wn + nt * 8 + tig * 2;
                float2 bb = *(const float2*)&bias[col];
                if (r0 < M) *(float2*)&C[(size_t)r0 * 128 + col] =
                    make_float2(acc[mt][nt][0] + bb.x, acc[mt][nt][1] + bb.y);
                if (r1 < M) *(float2*)&C[(size_t)r1 * 128 + col] =
                    make_float2(acc[mt][nt][2] + bb.x, acc[mt][nt][3] + bb.y);
            }
        }
        __syncthreads();
    }
}

// ---------------- fused gate GEMM + sigmoid + LN + leaky_relu -----------------
__global__ __launch_bounds__(256, 2)
void gate_ln(const float* __restrict__ o, const float* __restrict__ r,
             const __nv_bfloat16* __restrict__ w1, const __nv_bfloat16* __restrict__ w2,
             const float* __restrict__ bg, const float* __restrict__ lng,
             const float* __restrict__ lnb, float* __restrict__ out, int M)
{
    extern __shared__ char sm[];
    const int tid = threadIdx.x, wid = tid >> 5, lane = tid & 31;
    const int m0 = blockIdx.x * 64;
    const int wm = (wid >> 2) * 32, wn = (wid & 3) * 32;
    const int group = lane >> 2, tig = lane & 3;

    const uint32_t smb = smem_u32(sm);
    const uint32_t a_off = ((wm + (lane & 15)) * APAD + ((lane >> 4) << 3)) * 2;
    const uint32_t b_off = ((wn + ((lane >> 4) << 3) + (lane & 7)) * APAD + (((lane >> 3) & 1) << 3)) * 2;

    float acc[2][4][4];
    CLEAR_ACC(acc);

    // phase 0: o@W1 ; phase 1: r@W2 (accumulate)
    fill_A_f32(sm, o, m0, M, tid);
    fill_B(sm, w1, w1 + 16384, tid);
    __syncthreads();
    mma_tile(smb, a_off, b_off, acc);
    __syncthreads();

    fill_A_f32(sm, r, m0, M, tid);
    fill_B(sm, w2, w2 + 16384, tid);
    __syncthreads();
    mma_tile(smb, a_off, b_off, acc);
    __syncthreads();

    // hmix = o + sigmoid(gate)*(r - o) into smem buffer [64][132]
    float* hbuf = (float*)sm;
#pragma unroll
    for (int mt = 0; mt < 2; ++mt) {
        int lr0 = wm + mt * 16 + group, lr1 = lr0 + 8;
        int gr0 = m0 + lr0, gr1 = m0 + lr1;
#pragma unroll
        for (int nt = 0; nt < 4; ++nt) {
            int col = wn + nt * 8 + tig * 2;
            float2 bb = *(const float2*)&bg[col];
            if (gr0 < M) {
                float2 ov = *(const float2*)&o[(size_t)gr0 * 128 + col];
                float2 rv = *(const float2*)&r[(size_t)gr0 * 128 + col];
                float b0 = 1.f / (1.f + expf(-(acc[mt][nt][0] + bb.x)));
                float b1 = 1.f / (1.f + expf(-(acc[mt][nt][1] + bb.y)));
                hbuf[lr0 * 132 + col]     = ov.x + b0 * (rv.x - ov.x);
                hbuf[lr0 * 132 + col + 1] = ov.y + b1 * (rv.y - ov.y);
            }
            if (gr1 < M) {
                float2 ov = *(const float2*)&o[(size_t)gr1 * 128 + col];
                float2 rv = *(const float2*)&r[(size_t)gr1 * 128 + col];
                float b0 = 1.f / (1.f + expf(-(acc[mt][nt][2] + bb.x)));
                float b1 = 1.f / (1.f + expf(-(acc[mt][nt][3] + bb.y)));
                hbuf[lr1 * 132 + col]     = ov.x + b0 * (rv.x - ov.x);
                hbuf[lr1 * 132 + col + 1] = ov.y + b1 * (rv.y - ov.y);
            }
        }
    }
    __syncthreads();

    // per-row LayerNorm + leaky_relu (warp per row, 8 rows per warp)
#pragma unroll
    for (int i = 0; i < 8; ++i) {
        int row = wid * 8 + i;
        int gr = m0 + row;
        if (gr >= M) continue;
        float4 hv = *(float4*)&hbuf[row * 132 + lane * 4];
        float s1 = hv.x + hv.y + hv.z + hv.w;
        float s2 = hv.x * hv.x + hv.y * hv.y + hv.z * hv.z + hv.w * hv.w;
#pragma unroll
        for (int d = 16; d; d >>= 1) {
            s1 += __shfl_xor_sync(0xFFFFFFFFu, s1, d);
            s2 += __shfl_xor_sync(0xFFFFFFFFu, s2, d);
        }
        float mu = s1 * (1.f / 128.f);
        float var = s2 * (1.f / 128.f) - mu * mu;
        float inv = rsqrtf(var + 1e-5f);
        float4 gv = *(const float4*)&lng[lane * 4];
        float4 bv = *(const float4*)&lnb[lane * 4];
        float4 ov;
        ov.x = (hv.x - mu) * inv * gv.x + bv.x;
        ov.y = (hv.y - mu) * inv * gv.y + bv.y;
        ov.z = (hv.z - mu) * inv * gv.z + bv.z;
        ov.w = (hv.w - mu) * inv * gv.w + bv.w;
        ov.x = ov.x >= 0.f ? ov.x : 0.01f * ov.x;
        ov.y = ov.y >= 0.f ? ov.y : 0.01f * ov.y;
        ov.z = ov.z >= 0.f ? ov.z : 0.01f * ov.z;
        ov.w = ov.w >= 0.f ? ov.w : 0.01f * ov.w;
        *(float4*)&out[(size_t)gr * 128 + lane * 4] = ov;
    }
}

// ---------------- weight prep ---------------------------------------------------
__global__ void prep_w(const float* __restrict__ W, __nv_bfloat16* __restrict__ oh,
                       __nv_bfloat16* __restrict__ ol)
{
    int i = blockIdx.x * 256 + threadIdx.x;
    if (i < 16384) {
        int n = i >> 7, k = i & 127;
        float f = W[k * 128 + n];
        __nv_bfloat16 h = __float2bfloat16(f);
        oh[i] = h;
        ol[i] = __float2bfloat16(f - __bfloat162float(h));
    }
}

__global__ void prep_gate(const float* __restrict__ Wg,
                          __nv_bfloat16* __restrict__ o1h, __nv_bfloat16* __restrict__ o1l,
                          __nv_bfloat16* __restrict__ o2h, __nv_bfloat16* __restrict__ o2l)
{
    int i = blockIdx.x * 256 + threadIdx.x;
    if (i < 16384) {
        int n = i >> 7, k = i & 127;
        float bot = Wg[2 * 16384 + k * 128 + n];
        float f1 = Wg[k * 128 + n] + bot;
        float f2 = Wg[16384 + k * 128 + n] - bot;
        __nv_bfloat16 h1 = __float2bfloat16(f1);
        o1h[i] = h1;
        o1l[i] = __float2bfloat16(f1 - __bfloat162float(h1));
        __nv_bfloat16 h2 = __float2bfloat16(f2);
        o2h[i] = h2;
        o2l[i] = __float2bfloat16(f2 - __bfloat162float(h2));
    }
}

__global__ void prep_x(const float* __restrict__ X, __nv_bfloat16* __restrict__ xh,
                       __nv_bfloat16* __restrict__ xl, int n4)
{
    int i = blockIdx.x * 256 + threadIdx.x;
    if (i < n4) {
        float4 v = *(const float4*)&X[(size_t)i * 4];
        uint32_t hp0 = cvt2(v.x, v.y);
        uint32_t hp1 = cvt2(v.z, v.w);
        float lx = v.x - __uint_as_float(hp0 << 16);
        float ly = v.y - __uint_as_float(hp0 & 0xFFFF0000u);
        float lz = v.z - __uint_as_float(hp1 << 16);
        float lw = v.w - __uint_as_float(hp1 & 0xFFFF0000u);
        *(uint2*)&xh[(size_t)i * 4] = make_uint2(hp0, hp1);
        *(uint2*)&xl[(size_t)i * 4] = make_uint2(cvt2(lx, ly), cvt2(lz, lw));
    }
}

// ---------------- CSR build ---------------------------------------------------
__global__ void hist_kernel(const int* __restrict__ dst, int* __restrict__ counts, int E)
{
    int i = blockIdx.x * blockDim.x + threadIdx.x;
    if (i < E) atomicAdd(&counts[dst[i]], 1);
}

__global__ void scan_kernel(const int* __restrict__ counts, int* __restrict__ off,
                            int* __restrict__ cursor, int N)
{
    __shared__ int ssum[1024];
    int t = threadIdx.x;
    int chunk = (N + 1023) >> 10;
    int begin = t * chunk;
    int end = begin + chunk; if (end > N) end = N;
    int s = 0;
    for (int i = begin; i < end; ++i) s += counts[i];
    ssum[t] = s;
    __syncthreads();
    for (int d = 1; d < 1024; d <<= 1) {
        int v = (t >= d) ? ssum[t - d] : 0;
        __syncthreads();
        ssum[t] += v;
        __syncthreads();
    }
    int run = (t == 0) ? 0 : ssum[t - 1];
    for (int i = begin; i < end; ++i) {
        off[i] = run;
        cursor[i] = run;
        run += counts[i];
    }
    if (t == 1023) off[N] = ssum[1023];
}

__global__ void scatter_kernel(const int* __restrict__ dst, int* __restrict__ cursor,
                               int* __restrict__ elist, int E)
{
    int i = blockIdx.x * blockDim.x + threadIdx.x;
    if (i < E) {
        int p = atomicAdd(&cursor[dst[i]], 1);
        elist[p] = i;
    }
}

// ---------------- edge score ----------------------------------------------------
__global__ void edge_score(const float* __restrict__ e, const float* __restrict__ q,
                           const float* __restrict__ k, const int* __restrict__ src,
                           const int* __restrict__ dst, float* __restrict__ escore, int E)
{
    int w = (blockIdx.x * blockDim.x + threadIdx.x) >> 5;
    int lane = threadIdx.x & 31;
    if (w >= E) return;
    int s = src[w], dn = dst[w];
    float4 ev = *(const float4*)&e[(size_t)w * 128 + (lane << 2)];
    float4 kv = *(const float4*)&k[(size_t)s * 128 + (lane << 2)];
    float4 qv = *(const float4*)&q[(size_t)dn * 128 + (lane << 2)];
    float p = qv.x * (kv.x + ev.x) + qv.y * (kv.y + ev.y)
            + qv.z * (kv.z + ev.z) + qv.w * (kv.w + ev.w);
    p += __shfl_xor_sync(0xFFFFFFFFu, p, 1);
    p += __shfl_xor_sync(0xFFFFFFFFu, p, 2);
    if ((lane & 3) == 0) escore[(size_t)w * 8 + (lane >> 2)] = expf(p);
}

// ---------------- node aggregate + fused norm_escore output --------------------
__global__ void aggregate(const float* __restrict__ e, const float* __restrict__ v,
                          const float* __restrict__ escore, const int* __restrict__ src,
                          const int* __restrict__ off, const int* __restrict__ elist,
                          float* __restrict__ o, float* __restrict__ z,
                          float* __restrict__ out2, int N)
{
    int w = (blockIdx.x * blockDim.x + threadIdx.x) >> 5;
    int lane = threadIdx.x & 31;
    if (w >= N) return;
    int hl = lane >> 2;
    int beg = off[w], end = off[w + 1];
    float zl = 0.f;
    float ax = 0.f, ay = 0.f, az = 0.f, aw = 0.f;
    for (int idx = beg; idx < end; ++idx) {
        int eid = elist[idx];
        int s = src[eid];
        float esc = escore[(size_t)eid * 8 + hl];
        float4 ev = *(const float4*)&e[(size_t)eid * 128 + (lane << 2)];
        float4 vv = *(const float4*)&v[(size_t)s * 128 + (lane << 2)];
        zl += esc;
        ax += esc * (ev.x + vv.x);
        ay += esc * (ev.y + vv.y);
        az += esc * (ev.z + vv.z);
        aw += esc * (ev.w + vv.w);
    }
    float sc = 0.25f / (1e-8f + zl);
    float4 ov; ov.x = ax * sc; ov.y = ay * sc; ov.z = az * sc; ov.w = aw * sc;
    *(float4*)&o[(size_t)w * 128 + (lane << 2)] = ov;
    if ((lane & 3) == 0) z[(size_t)w * 8 + hl] = zl;
    // fused norm_escore: out2[eid,h] = 0.25*escore/(eps+z[dst])
    if ((lane & 3) == 0) {
        for (int idx = beg; idx < end; ++idx) {
            int eid = elist[idx];
            out2[(size_t)eid * 8 + hl] = sc * escore[(size_t)eid * 8 + hl];
        }
    }
}

// ---------------- launch ---------------------------------------------------------
extern "C" void kernel_launch(void* const* d_in, const int* in_sizes, int n_in,
                              void* d_out, int out_size)
{
    const float* x   = (const float*)d_in[0];
    const float* y   = (const float*)d_in[1];
    const int*   src = (const int*)d_in[2];
    const int*   dst = (const int*)d_in[3];
    const float* Wq  = (const float*)d_in[4];
    const float* bq  = (const float*)d_in[5];
    const float* Wk  = (const float*)d_in[6];
    const float* bk  = (const float*)d_in[7];
    const float* Wv  = (const float*)d_in[8];
    const float* bv  = (const float*)d_in[9];
    const float* We  = (const float*)d_in[10];
    const float* be  = (const float*)d_in[11];
    const float* Wr  = (const float*)d_in[12];
    const float* br  = (const float*)d_in[13];
    const float* Wg  = (const float*)d_in[14];
    const float* bg  = (const float*)d_in[15];
    const float* lng = (const float*)d_in[16];
    const float* lnb = (const float*)d_in[17];

    const int N = in_sizes[0] / 128;
    const int E = in_sizes[2];

    float *q, *k, *v, *r, *o, *e, *escore, *z;
    __nv_bfloat16 *wt, *xh, *xl;
    int *counts, *off, *cursor, *elist;
    void* p;
    cudaGetSymbolAddress(&p, g_q);      q = (float*)p;
    cudaGetSymbolAddress(&p, g_k);      k = (float*)p;
    cudaGetSymbolAddress(&p, g_v);      v = (float*)p;
    cudaGetSymbolAddress(&p, g_r);      r = (float*)p;
    cudaGetSymbolAddress(&p, g_o);      o = (float*)p;
    cudaGetSymbolAddress(&p, g_e);      e = (float*)p;
    cudaGetSymbolAddress(&p, g_escore); escore = (float*)p;
    cudaGetSymbolAddress(&p, g_z);      z = (float*)p;
    cudaGetSymbolAddress(&p, g_wt);     wt = (__nv_bfloat16*)p;
    cudaGetSymbolAddress(&p, g_xh);     xh = (__nv_bfloat16*)p;
    cudaGetSymbolAddress(&p, g_xl);     xl = (__nv_bfloat16*)p;
    cudaGetSymbolAddress(&p, g_counts); counts = (int*)p;
    cudaGetSymbolAddress(&p, g_off);    off = (int*)p;
    cudaGetSymbolAddress(&p, g_cursor); cursor = (int*)p;
    cudaGetSymbolAddress(&p, g_elist);  elist = (int*)p;

    cudaFuncSetAttribute(tc_gemm,   cudaFuncAttributeMaxDynamicSharedMemorySize, SMEM_G);
    cudaFuncSetAttribute(qkvr_gemm, cudaFuncAttributeMaxDynamicSharedMemorySize, SMEM_G);
    cudaFuncSetAttribute(gate_ln,   cudaFuncAttributeMaxDynamicSharedMemorySize, SMEM_G);

    float* out  = (float*)d_out;
    float* out2 = out + (size_t)N * 128;

    // weight slots: 0=q 1=k 2=v 3=r 4=e 5=W1 6=W2
    __nv_bfloat16* we_h = wt + 4 * 32768; __nv_bfloat16* we_l = we_h + 16384;
    __nv_bfloat16* w1_h = wt + 5 * 32768; __nv_bfloat16* w1_l = w1_h + 16384;
    __nv_bfloat16* w2_h = wt + 6 * 32768; __nv_bfloat16* w2_l = w2_h + 16384;

    const int gN = (N + 63) / 64;
    const int gE = (E + 63) / 64;

    // kernel index order (ncu -s 5 -c 1 captures index 5 = big e-GEMM)
    prep_x<<<(N * 32 + 255) / 256, 256>>>(x, xh, xl, N * 32);            // 0
    prep_w<<<64, 256>>>(We, we_h, we_l);                                 // 1
    prep_w<<<64, 256>>>(Wq, wt + 0 * 32768, wt + 0 * 32768 + 16384);     // 2
    prep_w<<<64, 256>>>(Wk, wt + 1 * 32768, wt + 1 * 32768 + 16384);     // 3
    prep_w<<<64, 256>>>(Wv, wt + 2 * 32768, wt + 2 * 32768 + 16384);     // 4
    tc_gemm<<<gE, 256, SMEM_G>>>(y, we_h, we_l, be, e, E);               // 5 <- profiled
    prep_w<<<64, 256>>>(Wr, wt + 3 * 32768, wt + 3 * 32768 + 16384);
    prep_gate<<<64, 256>>>(Wg, w1_h, w1_l, w2_h, w2_l);

    qkvr_gemm<<<gN, 256, SMEM_G>>>(xh, xl, wt, bq, bk, bv, br, q, k, v, r, N);

    // CSR build
    cudaMemsetAsync(counts, 0, (size_t)N * sizeof(int));
    hist_kernel<<<(E + 255) / 256, 256>>>(dst, counts, E);
    scan_kernel<<<1, 1024>>>(counts, off, cursor, N);
    scatter_kernel<<<(E + 255) / 256, 256>>>(dst, cursor, elist, E);

    // attention
    edge_score<<<(E + 7) / 8, 256>>>(e, q, k, src, dst, escore, E);
    aggregate<<<(N + 7) / 8, 256>>>(e, v, escore, src, off, elist, o, z, out2, N);

    // gated residual + LN + leaky (fused)
    gate_ln<<<gN, 256, SMEM_G>>>(o, r, w1_h, w2_h, bg, lng, lnb, out, N);
}